// round 14
// baseline (speedup 1.0000x reference)
#include <cuda_runtime.h>
#include <cuda_fp16.h>
#include <cstdint>

static constexpr int B_ = 8, T_ = 2048, S_ = 2048, H_ = 64;
static constexpr int NT = 256;

// per-row (m_ref, coef) scratch between the two kernels
__device__ float2 g_mc[B_ * T_];

// ---------- K1 smem layout (u32 units) ----------
static constexpr int KHI = 0;        // K hi: [s:128][pos:32] stride 40, pair-interleaved
static constexpr int KLO = 5120;
static constexpr int VHI = 10240;    // V hi: [h:64][pos:64] stride 72, interleave + XOR swizzle
static constexpr int CIDXU  = 14848;
static constexpr int BITARR = 15936;
static constexpr int OFFU   = 16000;
static constexpr int RINV   = 16064;
static constexpr int LBUF   = 16128;
static constexpr int MBUF   = 16256;
static constexpr int SEFFU  = 16384;
static constexpr int SMEMU  = 16388;
static constexpr int SMEM_BYTES = SMEMU * 4;   // ~64 KB -> 2 CTAs/SM
static constexpr int OBUF = 0;

// ---------- K2 smem layout ----------
static constexpr int BITARR2 = 10240;
static constexpr int SMEMU2  = 10304;
static constexpr int SMEM2_BYTES = SMEMU2 * 4; // ~41 KB -> 3 CTAs/SM

__device__ __forceinline__ void mma16(float* d, const uint32_t* a, uint32_t b0, uint32_t b1) {
    asm volatile(
        "mma.sync.aligned.m16n8k16.row.col.f32.f16.f16.f32 "
        "{%0,%1,%2,%3}, {%4,%5,%6,%7}, {%8,%9}, {%0,%1,%2,%3};"
        : "+f"(d[0]), "+f"(d[1]), "+f"(d[2]), "+f"(d[3])
        : "r"(a[0]), "r"(a[1]), "r"(a[2]), "r"(a[3]), "r"(b0), "r"(b1));
}

__device__ __forceinline__ uint32_t packhl(float x, float y, uint32_t& lo) {
    __half hx = __float2half_rn(x), hy = __float2half_rn(y);
    __half2 L = __floats2half2_rn(x - __half2float(hx), y - __half2float(hy));
    __half2 Hh = __halves2half2(hx, hy);
    lo = *(uint32_t*)&L;
    return *(uint32_t*)&Hh;
}

__device__ __forceinline__ uint32_t packh(float x, float y) {
    __half2 Hh = __floats2half2_rn(x, y);
    return *(uint32_t*)&Hh;
}

__device__ __forceinline__ int swzv(int h) {
    return ((h & 3) << 1) ^ (((h >> 2) & 7) << 2);
}

extern __shared__ uint32_t smu[];

// ===================== K1: stats + O (compacted flash) =====================
__global__ void __launch_bounds__(NT, 2)
attn_p1(const float* __restrict__ q, const float* __restrict__ k,
        const float* __restrict__ v, const int* __restrict__ mask,
        float* __restrict__ out)
{
    const int tid = threadIdx.x;
    const int w = tid >> 5, lane = tid & 31;
    const int n_ = lane >> 2, tm = lane & 3;
    const int bx = blockIdx.x;
    const int b = bx >> 5, t0 = (bx & 31) << 6;
    const int slab = w & 3, shalf = w >> 2;

    const float* qb = q + ((size_t)b * T_ + t0) * H_;
    const float* kb = k + (size_t)b * S_ * H_;
    const float* vb = v + (size_t)b * S_ * H_;
    const int*   mb = mask + (size_t)b * S_;
    float* oo = out + ((size_t)b * T_ + t0) * H_;

    float* smf = (float*)smu;
    unsigned short* cidx = (unsigned short*)(smu + CIDXU);
    const int prow = 16 * slab + n_;

    uint32_t qh[4][4], ql[4][4];
    #pragma unroll
    for (int kc = 0; kc < 4; kc++) {
        const int base = kc * 16 + 2 * tm;
        float2 x0 = *(const float2*)(qb + prow * 64 + base);
        float2 x1 = *(const float2*)(qb + (prow + 8) * 64 + base);
        float2 x2 = *(const float2*)(qb + prow * 64 + base + 8);
        float2 x3 = *(const float2*)(qb + (prow + 8) * 64 + base + 8);
        qh[kc][0] = packhl(x0.x, x0.y, ql[kc][0]);
        qh[kc][1] = packhl(x1.x, x1.y, ql[kc][1]);
        qh[kc][2] = packhl(x2.x, x2.y, ql[kc][2]);
        qh[kc][3] = packhl(x3.x, x3.y, ql[kc][3]);
    }

    #pragma unroll
    for (int i = 0; i < 8; i++) {
        int s = i * 256 + tid;
        unsigned bal = __ballot_sync(0xffffffffu, mb[s] != 0);
        if (lane == 0) smu[BITARR + i * 8 + w] = bal;
    }
    __syncthreads();
    if (tid == 0) {
        int acc = 0;
        for (int c = 0; c < 64; c++) { smu[OFFU + c] = acc; acc += __popc(smu[BITARR + c]); }
        smu[SEFFU] = acc;
    }
    __syncthreads();
    const int seff = (int)smu[SEFFU];
    const int ntiles = (seff + 127) >> 7;
    const int npad = ntiles << 7;
    if (tid < 64) {
        uint32_t bits = smu[BITARR + tid];
        int o = (int)smu[OFFU + tid];
        int base = tid * 32;
        while (bits) { int bb = __ffs(bits) - 1; cidx[o++] = (unsigned short)(base + bb); bits &= bits - 1; }
    }
    for (int i = tid; i < npad; i += NT) if (i >= seff) cidx[i] = 0xFFFFu;

    float O[8][4];
    #pragma unroll
    for (int i = 0; i < 8; i++)
        #pragma unroll
        for (int jj = 0; jj < 4; jj++) O[i][jj] = 0.0f;
    float m0 = -3.0e38f, m1 = -3.0e38f, lm0 = 0.0f, lm1 = 0.0f;
    float em0 = 0.0f, em1 = 0.0f;
    const float LOGT = 10.0f;

    const int ks_s  = tid >> 4;
    const int ks_k4 = (tid & 15) * 4;
    const int kt0 = ks_k4 >> 1;
    const int kpb = kt0 & ~7;
    const int ku0 = kt0 & 7;
    const int kp0 = kpb + 2 * (ku0 & 3) + (ku0 >> 2);
    const int kp1 = kp0 + 2;
    const int vs_spb = w * 2 + (lane >> 4);
    const int vs_cc  = 4 * (lane & 15);

    for (int j = 0; j < ntiles; j++) {
        const int s0c = j << 7;
        __syncthreads();

        #pragma unroll
        for (int it = 0; it < 8; it++) {
            int s = ks_s + it * 16;
            int orig = cidx[s0c + s];
            float4 x = make_float4(0.f, 0.f, 0.f, 0.f);
            if (orig != 0xFFFF) x = *(const float4*)(kb + (size_t)orig * H_ + ks_k4);
            uint32_t l0, l1;
            uint32_t h0 = packhl(x.x, x.y, l0);
            uint32_t h1 = packhl(x.z, x.w, l1);
            smu[KHI + s * 40 + kp0] = h0;
            smu[KHI + s * 40 + kp1] = h1;
            smu[KLO + s * 40 + kp0] = l0;
            smu[KLO + s * 40 + kp1] = l1;
        }
        #pragma unroll
        for (int it = 0; it < 4; it++) {
            int sp = vs_spb + it * 16;
            int o0 = cidx[s0c + 2 * sp], o1 = cidx[s0c + 2 * sp + 1];
            float4 a  = make_float4(0.f, 0.f, 0.f, 0.f);
            float4 b4 = make_float4(0.f, 0.f, 0.f, 0.f);
            if (o0 != 0xFFFF) a  = *(const float4*)(vb + (size_t)o0 * H_ + vs_cc);
            if (o1 != 0xFFFF) b4 = *(const float4*)(vb + (size_t)o1 * H_ + vs_cc);
            int qp = (sp & ~7) + 2 * (sp & 3) + ((sp >> 2) & 1);
            smu[VHI + (vs_cc + 0) * 72 + (qp ^ swzv(vs_cc + 0))] = packh(a.x, b4.x);
            smu[VHI + (vs_cc + 1) * 72 + (qp ^ swzv(vs_cc + 1))] = packh(a.y, b4.y);
            smu[VHI + (vs_cc + 2) * 72 + (qp ^ swzv(vs_cc + 2))] = packh(a.z, b4.z);
            smu[VHI + (vs_cc + 3) * 72 + (qp ^ swzv(vs_cc + 3))] = packh(a.w, b4.w);
        }
        __syncthreads();

        #pragma unroll 2
        for (int ntp = 0; ntp < 4; ntp++) {
            const int ntpg = shalf * 4 + ntp;
            float sv[2][4];
            bool bt[2][2];
            #pragma unroll
            for (int si = 0; si < 2; si++) {
                const int strip = ntpg * 2 + si;
                float dh[4] = {0.f,0.f,0.f,0.f}, dm[4] = {0.f,0.f,0.f,0.f}, dl[4] = {0.f,0.f,0.f,0.f};
                const int kb0 = (strip * 8 + n_) * 40 + 2 * tm;
                #pragma unroll
                for (int kc = 0; kc < 4; kc++) {
                    uint2 bh = *(const uint2*)&smu[KHI + kb0 + kc * 8];
                    uint2 bl = *(const uint2*)&smu[KLO + kb0 + kc * 8];
                    mma16(dh, qh[kc], bh.x, bh.y);
                    mma16(dm, ql[kc], bh.x, bh.y);
                    mma16(dl, qh[kc], bl.x, bl.y);
                }
                #pragma unroll
                for (int x = 0; x < 4; x++) sv[si][x] = dh[x] + dm[x] + dl[x];
                const int cg = strip * 8 + 2 * tm;
                uint32_t pr = *(const uint32_t*)&cidx[s0c + cg];
                bt[si][0] = ((pr & 0xFFFFu) != 0xFFFFu);
                bt[si][1] = ((pr >> 16) != 0xFFFFu);
            }
            float t0_ = -3.0e38f, t1_ = -3.0e38f;
            #pragma unroll
            for (int si = 0; si < 2; si++) {
                if (bt[si][0]) { t0_ = fmaxf(t0_, sv[si][0]); t1_ = fmaxf(t1_, sv[si][2]); }
                if (bt[si][1]) { t0_ = fmaxf(t0_, sv[si][1]); t1_ = fmaxf(t1_, sv[si][3]); }
            }
            bool big = (t0_ > m0 + LOGT) || (t1_ > m1 + LOGT);
            if (__any_sync(0xffffffffu, big)) {
                t0_ = fmaxf(t0_, __shfl_xor_sync(0xffffffffu, t0_, 1));
                t0_ = fmaxf(t0_, __shfl_xor_sync(0xffffffffu, t0_, 2));
                t1_ = fmaxf(t1_, __shfl_xor_sync(0xffffffffu, t1_, 1));
                t1_ = fmaxf(t1_, __shfl_xor_sync(0xffffffffu, t1_, 2));
                float m0n = fmaxf(m0, t0_), m1n = fmaxf(m1, t1_);
                float f0 = __expf(m0 - m0n), f1 = __expf(m1 - m1n);
                lm0 *= f0; lm1 *= f1;
                #pragma unroll
                for (int vt = 0; vt < 8; vt++) {
                    O[vt][0] *= f0; O[vt][1] *= f0;
                    O[vt][2] *= f1; O[vt][3] *= f1;
                }
                m0 = m0n; m1 = m1n;
                em0 = __expf(m0); em1 = __expf(m1);
            }

            float e[2][4];
            #pragma unroll
            for (int si = 0; si < 2; si++) {
                e[si][0] = bt[si][0] ? __expf(sv[si][0] - m0) : 0.0f;
                e[si][1] = bt[si][1] ? __expf(sv[si][1] - m0) : 0.0f;
                e[si][2] = bt[si][0] ? __expf(sv[si][2] - m1) : 0.0f;
                e[si][3] = bt[si][1] ? __expf(sv[si][3] - m1) : 0.0f;
                lm0 += e[si][0] + e[si][1];
                lm1 += e[si][2] + e[si][3];
            }
            uint32_t pah[4], pal[4];
            pah[0] = packhl(e[0][0], e[0][1], pal[0]);
            pah[1] = packhl(e[0][2], e[0][3], pal[1]);
            pah[2] = packhl(e[1][0], e[1][1], pal[2]);
            pah[3] = packhl(e[1][2], e[1][3], pal[3]);

            const int xbase = ntpg * 8 + 2 * tm;
            #pragma unroll
            for (int vt = 0; vt < 8; vt++) {
                const int h = vt * 8 + n_;
                uint2 vv = *(const uint2*)&smu[VHI + h * 72 + (xbase ^ swzv(h))];
                mma16(O[vt], pah, vv.x, vv.y);
                mma16(O[vt], pal, vv.x, vv.y);
            }
        }
    }

    // ---- epilogue: combine halves, write O and per-row (m_ref, coef) ----
    lm0 += __shfl_xor_sync(0xffffffffu, lm0, 1);
    lm0 += __shfl_xor_sync(0xffffffffu, lm0, 2);
    lm1 += __shfl_xor_sync(0xffffffffu, lm1, 1);
    lm1 += __shfl_xor_sync(0xffffffffu, lm1, 2);

    #pragma unroll
    for (int vt = 0; vt < 8; vt++) {
        O[vt][0] *= em0; O[vt][1] *= em0;
        O[vt][2] *= em1; O[vt][3] *= em1;
    }

    __syncthreads();
    if (tm == 0) {
        smf[LBUF + shalf * 64 + prow]     = lm0 * em0;
        smf[LBUF + shalf * 64 + prow + 8] = lm1 * em1;
        smf[MBUF + shalf * 64 + prow]     = m0;
        smf[MBUF + shalf * 64 + prow + 8] = m1;
    }
    if (shalf == 0) {
        #pragma unroll
        for (int vt = 0; vt < 8; vt++) {
            int c = vt * 8 + 2 * tm;
            *(float2*)&smf[OBUF + prow * 68 + c]       = make_float2(O[vt][0], O[vt][1]);
            *(float2*)&smf[OBUF + (prow + 8) * 68 + c] = make_float2(O[vt][2], O[vt][3]);
        }
    }
    __syncthreads();
    if (tid < 64) {
        float inv = 1.0f / (smf[LBUF + tid] + smf[LBUF + 64 + tid]);
        smf[RINV + tid] = inv;
        float mr = fmaxf(smf[MBUF + tid], smf[MBUF + 64 + tid]);
        g_mc[(size_t)b * T_ + t0 + tid] = make_float2(mr, __expf(mr) * inv);
    }
    __syncthreads();

    if (shalf == 1) {
        const float iv0 = smf[RINV + prow];
        const float iv1 = smf[RINV + prow + 8];
        #pragma unroll
        for (int vt = 0; vt < 8; vt++) {
            int c = vt * 8 + 2 * tm;
            float2 pa = *(const float2*)&smf[OBUF + prow * 68 + c];
            float2 pb = *(const float2*)&smf[OBUF + (prow + 8) * 68 + c];
            *(float2*)(oo + (size_t)prow * H_ + c) =
                make_float2((pa.x + O[vt][0]) * iv0, (pa.y + O[vt][1]) * iv0);
            *(float2*)(oo + (size_t)(prow + 8) * H_ + c) =
                make_float2((pb.x + O[vt][2]) * iv1, (pb.y + O[vt][3]) * iv1);
        }
    }
}

// ===================== K2: recompute scores, write final p =====================
__global__ void __launch_bounds__(NT, 3)
attn_p2(const float* __restrict__ q, const float* __restrict__ k,
        const int* __restrict__ mask, float* __restrict__ out)
{
    const int tid = threadIdx.x;
    const int w = tid >> 5, lane = tid & 31;
    const int n_ = lane >> 2, tm = lane & 3;
    const int bx = blockIdx.x;
    const int b = bx >> 5, t0 = (bx & 31) << 6;
    const int slab = w & 3, shalf = w >> 2;

    const float* qb = q + ((size_t)b * T_ + t0) * H_;
    const float* kb = k + (size_t)b * S_ * H_;
    const int*   mb = mask + (size_t)b * S_;
    float* pp = out + (size_t)B_ * T_ * H_ + ((size_t)b * T_ + t0) * S_;

    const int prow = 16 * slab + n_;

    uint32_t qh[4][4], ql[4][4];
    #pragma unroll
    for (int kc = 0; kc < 4; kc++) {
        const int base = kc * 16 + 2 * tm;
        float2 x0 = *(const float2*)(qb + prow * 64 + base);
        float2 x1 = *(const float2*)(qb + (prow + 8) * 64 + base);
        float2 x2 = *(const float2*)(qb + prow * 64 + base + 8);
        float2 x3 = *(const float2*)(qb + (prow + 8) * 64 + base + 8);
        qh[kc][0] = packhl(x0.x, x0.y, ql[kc][0]);
        qh[kc][1] = packhl(x1.x, x1.y, ql[kc][1]);
        qh[kc][2] = packhl(x2.x, x2.y, ql[kc][2]);
        qh[kc][3] = packhl(x3.x, x3.y, ql[kc][3]);
    }

    float2 mc0 = g_mc[(size_t)b * T_ + t0 + prow];
    float2 mc1 = g_mc[(size_t)b * T_ + t0 + prow + 8];
    const float mr0 = mc0.x, cf0 = mc0.y;
    const float mr1 = mc1.x, cf1 = mc1.y;

    #pragma unroll
    for (int i = 0; i < 8; i++) {
        int s = i * 256 + tid;
        unsigned bal = __ballot_sync(0xffffffffu, mb[s] != 0);
        if (lane == 0) smu[BITARR2 + i * 8 + w] = bal;
    }

    const int ks_s  = tid >> 4;
    const int ks_k4 = (tid & 15) * 4;
    const int kt0 = ks_k4 >> 1;
    const int kpb = kt0 & ~7;
    const int ku0 = kt0 & 7;
    const int kp0 = kpb + 2 * (ku0 & 3) + (ku0 >> 2);
    const int kp1 = kp0 + 2;

    for (int j = 0; j < 16; j++) {
        const int s0 = j << 7;
        __syncthreads();

        const float* kt = kb + (size_t)s0 * H_;
        #pragma unroll
        for (int it = 0; it < 8; it++) {
            int s = ks_s + it * 16;
            float4 x = *(const float4*)(kt + s * 64 + ks_k4);
            uint32_t l0, l1;
            uint32_t h0 = packhl(x.x, x.y, l0);
            uint32_t h1 = packhl(x.z, x.w, l1);
            smu[KHI + s * 40 + kp0] = h0;
            smu[KHI + s * 40 + kp1] = h1;
            smu[KLO + s * 40 + kp0] = l0;
            smu[KLO + s * 40 + kp1] = l1;
        }
        __syncthreads();

        #pragma unroll 2
        for (int ntp = 0; ntp < 4; ntp++) {
            const int ntpg = shalf * 4 + ntp;
            #pragma unroll
            for (int si = 0; si < 2; si++) {
                const int strip = ntpg * 2 + si;
                float dh[4] = {0.f,0.f,0.f,0.f}, dm[4] = {0.f,0.f,0.f,0.f}, dl[4] = {0.f,0.f,0.f,0.f};
                const int kb0 = (strip * 8 + n_) * 40 + 2 * tm;
                #pragma unroll
                for (int kc = 0; kc < 4; kc++) {
                    uint2 bh = *(const uint2*)&smu[KHI + kb0 + kc * 8];
                    uint2 bl = *(const uint2*)&smu[KLO + kb0 + kc * 8];
                    mma16(dh, qh[kc], bh.x, bh.y);
                    mma16(dm, ql[kc], bh.x, bh.y);
                    mma16(dl, qh[kc], bl.x, bl.y);
                }
                const int cg = strip * 8 + 2 * tm;
                uint32_t wb = smu[BITARR2 + j * 4 + (strip >> 2)];
                int sh = ((strip & 3) << 3) + 2 * tm;
                bool b0 = (wb >> sh) & 1u, b1 = (wb >> (sh + 1)) & 1u;
                float s00 = dh[0] + dm[0] + dl[0];
                float s01 = dh[1] + dm[1] + dl[1];
                float s10 = dh[2] + dm[2] + dl[2];
                float s11 = dh[3] + dm[3] + dl[3];
                float p00 = b0 ? __expf(s00 - mr0) * cf0 : 0.0f;
                float p01 = b1 ? __expf(s01 - mr0) * cf0 : 0.0f;
                float p10 = b0 ? __expf(s10 - mr1) * cf1 : 0.0f;
                float p11 = b1 ? __expf(s11 - mr1) * cf1 : 0.0f;
                __stcs((float2*)(pp + (size_t)prow * S_ + s0 + cg), make_float2(p00, p01));
                __stcs((float2*)(pp + (size_t)(prow + 8) * S_ + s0 + cg), make_float2(p10, p11));
            }
        }
    }
}

extern "C" void kernel_launch(void* const* d_in, const int* in_sizes, int n_in,
                              void* d_out, int out_size)
{
    const float* q    = (const float*)d_in[0];
    const float* keys = (const float*)d_in[1];
    const float* vals = (const float*)d_in[2];
    const int*   mask = (const int*)d_in[3];
    float* out = (float*)d_out;

    cudaFuncSetAttribute(attn_p1, cudaFuncAttributeMaxDynamicSharedMemorySize, SMEM_BYTES);
    cudaFuncSetAttribute(attn_p2, cudaFuncAttributeMaxDynamicSharedMemorySize, SMEM2_BYTES);
    attn_p1<<<B_ * (T_ / 64), NT, SMEM_BYTES>>>(q, keys, vals, mask, out);
    attn_p2<<<B_ * (T_ / 64), NT, SMEM2_BYTES>>>(q, keys, mask, out);
}

// round 15
// speedup vs baseline: 1.0062x; 1.0062x over previous
#include <cuda_runtime.h>
#include <cuda_fp16.h>
#include <cstdint>

static constexpr int B_ = 8, T_ = 2048, S_ = 2048, H_ = 64;
static constexpr int NT = 256;

// per-row (m_ref, coef) scratch between the two kernels
__device__ float2 g_mc[B_ * T_];

// ---------- K1 smem layout (u32 units) ----------
static constexpr int KHI = 0;        // K hi: [s:128][pos:32] stride 40, pair-interleaved
static constexpr int KLO = 5120;
static constexpr int VHI = 10240;    // V hi: [h:64][pos:64] stride 72, interleave + XOR swizzle
static constexpr int CIDXU  = 14848;
static constexpr int BITARR = 15936;
static constexpr int OFFU   = 16000;
static constexpr int RINV   = 16064;
static constexpr int LBUF   = 16128;
static constexpr int MBUF   = 16256;
static constexpr int SEFFU  = 16384;
static constexpr int SMEMU  = 16388;
static constexpr int SMEM_BYTES = SMEMU * 4;   // ~64 KB -> 2 CTAs/SM
static constexpr int OBUF = 0;

// ---------- K2 smem layout ----------
static constexpr int BITARR2 = 10240;
static constexpr int SMEMU2  = 10304;
static constexpr int SMEM2_BYTES = SMEMU2 * 4; // ~41 KB

__device__ __forceinline__ void mma16(float* d, const uint32_t* a, uint32_t b0, uint32_t b1) {
    asm volatile(
        "mma.sync.aligned.m16n8k16.row.col.f32.f16.f16.f32 "
        "{%0,%1,%2,%3}, {%4,%5,%6,%7}, {%8,%9}, {%0,%1,%2,%3};"
        : "+f"(d[0]), "+f"(d[1]), "+f"(d[2]), "+f"(d[3])
        : "r"(a[0]), "r"(a[1]), "r"(a[2]), "r"(a[3]), "r"(b0), "r"(b1));
}

__device__ __forceinline__ uint32_t packhl(float x, float y, uint32_t& lo) {
    __half hx = __float2half_rn(x), hy = __float2half_rn(y);
    __half2 L = __floats2half2_rn(x - __half2float(hx), y - __half2float(hy));
    __half2 Hh = __halves2half2(hx, hy);
    lo = *(uint32_t*)&L;
    return *(uint32_t*)&Hh;
}

__device__ __forceinline__ uint32_t packh(float x, float y) {
    __half2 Hh = __floats2half2_rn(x, y);
    return *(uint32_t*)&Hh;
}

__device__ __forceinline__ int swzv(int h) {
    return ((h & 3) << 1) ^ (((h >> 2) & 7) << 2);
}

extern __shared__ uint32_t smu[];

// ===================== K1: stats + O (compacted flash) =====================
__global__ void __launch_bounds__(NT, 2)
attn_p1(const float* __restrict__ q, const float* __restrict__ k,
        const float* __restrict__ v, const int* __restrict__ mask,
        float* __restrict__ out)
{
    const int tid = threadIdx.x;
    const int w = tid >> 5, lane = tid & 31;
    const int n_ = lane >> 2, tm = lane & 3;
    const int bx = blockIdx.x;
    const int b = bx >> 5, t0 = (bx & 31) << 6;
    const int slab = w & 3, shalf = w >> 2;

    const float* qb = q + ((size_t)b * T_ + t0) * H_;
    const float* kb = k + (size_t)b * S_ * H_;
    const float* vb = v + (size_t)b * S_ * H_;
    const int*   mb = mask + (size_t)b * S_;
    float* oo = out + ((size_t)b * T_ + t0) * H_;

    float* smf = (float*)smu;
    unsigned short* cidx = (unsigned short*)(smu + CIDXU);
    const int prow = 16 * slab + n_;

    uint32_t qh[4][4], ql[4][4];
    #pragma unroll
    for (int kc = 0; kc < 4; kc++) {
        const int base = kc * 16 + 2 * tm;
        float2 x0 = *(const float2*)(qb + prow * 64 + base);
        float2 x1 = *(const float2*)(qb + (prow + 8) * 64 + base);
        float2 x2 = *(const float2*)(qb + prow * 64 + base + 8);
        float2 x3 = *(const float2*)(qb + (prow + 8) * 64 + base + 8);
        qh[kc][0] = packhl(x0.x, x0.y, ql[kc][0]);
        qh[kc][1] = packhl(x1.x, x1.y, ql[kc][1]);
        qh[kc][2] = packhl(x2.x, x2.y, ql[kc][2]);
        qh[kc][3] = packhl(x3.x, x3.y, ql[kc][3]);
    }

    #pragma unroll
    for (int i = 0; i < 8; i++) {
        int s = i * 256 + tid;
        unsigned bal = __ballot_sync(0xffffffffu, mb[s] != 0);
        if (lane == 0) smu[BITARR + i * 8 + w] = bal;
    }
    __syncthreads();
    if (tid == 0) {
        int acc = 0;
        for (int c = 0; c < 64; c++) { smu[OFFU + c] = acc; acc += __popc(smu[BITARR + c]); }
        smu[SEFFU] = acc;
    }
    __syncthreads();
    const int seff = (int)smu[SEFFU];
    const int ntiles = (seff + 127) >> 7;
    const int npad = ntiles << 7;
    if (tid < 64) {
        uint32_t bits = smu[BITARR + tid];
        int o = (int)smu[OFFU + tid];
        int base = tid * 32;
        while (bits) { int bb = __ffs(bits) - 1; cidx[o++] = (unsigned short)(base + bb); bits &= bits - 1; }
    }
    for (int i = tid; i < npad; i += NT) if (i >= seff) cidx[i] = 0xFFFFu;

    float O[8][4];
    #pragma unroll
    for (int i = 0; i < 8; i++)
        #pragma unroll
        for (int jj = 0; jj < 4; jj++) O[i][jj] = 0.0f;
    float m0 = -3.0e38f, m1 = -3.0e38f, lm0 = 0.0f, lm1 = 0.0f;
    float em0 = 0.0f, em1 = 0.0f;
    const float LOGT = 10.0f;

    const int ks_s  = tid >> 4;
    const int ks_k4 = (tid & 15) * 4;
    const int kt0 = ks_k4 >> 1;
    const int kpb = kt0 & ~7;
    const int ku0 = kt0 & 7;
    const int kp0 = kpb + 2 * (ku0 & 3) + (ku0 >> 2);
    const int kp1 = kp0 + 2;
    const int vs_spb = w * 2 + (lane >> 4);
    const int vs_cc  = 4 * (lane & 15);

    for (int j = 0; j < ntiles; j++) {
        const int s0c = j << 7;
        __syncthreads();

        #pragma unroll
        for (int it = 0; it < 8; it++) {
            int s = ks_s + it * 16;
            int orig = cidx[s0c + s];
            float4 x = make_float4(0.f, 0.f, 0.f, 0.f);
            if (orig != 0xFFFF) x = *(const float4*)(kb + (size_t)orig * H_ + ks_k4);
            uint32_t l0, l1;
            uint32_t h0 = packhl(x.x, x.y, l0);
            uint32_t h1 = packhl(x.z, x.w, l1);
            smu[KHI + s * 40 + kp0] = h0;
            smu[KHI + s * 40 + kp1] = h1;
            smu[KLO + s * 40 + kp0] = l0;
            smu[KLO + s * 40 + kp1] = l1;
        }
        #pragma unroll
        for (int it = 0; it < 4; it++) {
            int sp = vs_spb + it * 16;
            int o0 = cidx[s0c + 2 * sp], o1 = cidx[s0c + 2 * sp + 1];
            float4 a  = make_float4(0.f, 0.f, 0.f, 0.f);
            float4 b4 = make_float4(0.f, 0.f, 0.f, 0.f);
            if (o0 != 0xFFFF) a  = *(const float4*)(vb + (size_t)o0 * H_ + vs_cc);
            if (o1 != 0xFFFF) b4 = *(const float4*)(vb + (size_t)o1 * H_ + vs_cc);
            int qp = (sp & ~7) + 2 * (sp & 3) + ((sp >> 2) & 1);
            smu[VHI + (vs_cc + 0) * 72 + (qp ^ swzv(vs_cc + 0))] = packh(a.x, b4.x);
            smu[VHI + (vs_cc + 1) * 72 + (qp ^ swzv(vs_cc + 1))] = packh(a.y, b4.y);
            smu[VHI + (vs_cc + 2) * 72 + (qp ^ swzv(vs_cc + 2))] = packh(a.z, b4.z);
            smu[VHI + (vs_cc + 3) * 72 + (qp ^ swzv(vs_cc + 3))] = packh(a.w, b4.w);
        }
        __syncthreads();

        #pragma unroll 2
        for (int ntp = 0; ntp < 4; ntp++) {
            const int ntpg = shalf * 4 + ntp;
            float sv[2][4];
            bool bt[2][2];
            #pragma unroll
            for (int si = 0; si < 2; si++) {
                const int strip = ntpg * 2 + si;
                float dh[4] = {0.f,0.f,0.f,0.f}, dm[4] = {0.f,0.f,0.f,0.f}, dl[4] = {0.f,0.f,0.f,0.f};
                const int kb0 = (strip * 8 + n_) * 40 + 2 * tm;
                #pragma unroll
                for (int kc = 0; kc < 4; kc++) {
                    uint2 bh = *(const uint2*)&smu[KHI + kb0 + kc * 8];
                    uint2 bl = *(const uint2*)&smu[KLO + kb0 + kc * 8];
                    mma16(dh, qh[kc], bh.x, bh.y);
                    mma16(dm, ql[kc], bh.x, bh.y);
                    mma16(dl, qh[kc], bl.x, bl.y);
                }
                #pragma unroll
                for (int x = 0; x < 4; x++) sv[si][x] = dh[x] + dm[x] + dl[x];
                const int cg = strip * 8 + 2 * tm;
                uint32_t pr = *(const uint32_t*)&cidx[s0c + cg];
                bt[si][0] = ((pr & 0xFFFFu) != 0xFFFFu);
                bt[si][1] = ((pr >> 16) != 0xFFFFu);
            }
            float t0_ = -3.0e38f, t1_ = -3.0e38f;
            #pragma unroll
            for (int si = 0; si < 2; si++) {
                if (bt[si][0]) { t0_ = fmaxf(t0_, sv[si][0]); t1_ = fmaxf(t1_, sv[si][2]); }
                if (bt[si][1]) { t0_ = fmaxf(t0_, sv[si][1]); t1_ = fmaxf(t1_, sv[si][3]); }
            }
            bool big = (t0_ > m0 + LOGT) || (t1_ > m1 + LOGT);
            if (__any_sync(0xffffffffu, big)) {
                t0_ = fmaxf(t0_, __shfl_xor_sync(0xffffffffu, t0_, 1));
                t0_ = fmaxf(t0_, __shfl_xor_sync(0xffffffffu, t0_, 2));
                t1_ = fmaxf(t1_, __shfl_xor_sync(0xffffffffu, t1_, 1));
                t1_ = fmaxf(t1_, __shfl_xor_sync(0xffffffffu, t1_, 2));
                float m0n = fmaxf(m0, t0_), m1n = fmaxf(m1, t1_);
                float f0 = __expf(m0 - m0n), f1 = __expf(m1 - m1n);
                lm0 *= f0; lm1 *= f1;
                #pragma unroll
                for (int vt = 0; vt < 8; vt++) {
                    O[vt][0] *= f0; O[vt][1] *= f0;
                    O[vt][2] *= f1; O[vt][3] *= f1;
                }
                m0 = m0n; m1 = m1n;
                em0 = __expf(m0); em1 = __expf(m1);
            }

            float e[2][4];
            #pragma unroll
            for (int si = 0; si < 2; si++) {
                e[si][0] = bt[si][0] ? __expf(sv[si][0] - m0) : 0.0f;
                e[si][1] = bt[si][1] ? __expf(sv[si][1] - m0) : 0.0f;
                e[si][2] = bt[si][0] ? __expf(sv[si][2] - m1) : 0.0f;
                e[si][3] = bt[si][1] ? __expf(sv[si][3] - m1) : 0.0f;
                lm0 += e[si][0] + e[si][1];
                lm1 += e[si][2] + e[si][3];
            }
            uint32_t pah[4], pal[4];
            pah[0] = packhl(e[0][0], e[0][1], pal[0]);
            pah[1] = packhl(e[0][2], e[0][3], pal[1]);
            pah[2] = packhl(e[1][0], e[1][1], pal[2]);
            pah[3] = packhl(e[1][2], e[1][3], pal[3]);

            const int xbase = ntpg * 8 + 2 * tm;
            #pragma unroll
            for (int vt = 0; vt < 8; vt++) {
                const int h = vt * 8 + n_;
                uint2 vv = *(const uint2*)&smu[VHI + h * 72 + (xbase ^ swzv(h))];
                mma16(O[vt], pah, vv.x, vv.y);
                mma16(O[vt], pal, vv.x, vv.y);
            }
        }
    }

    // ---- epilogue: combine halves, write O and per-row (m_ref, coef) ----
    lm0 += __shfl_xor_sync(0xffffffffu, lm0, 1);
    lm0 += __shfl_xor_sync(0xffffffffu, lm0, 2);
    lm1 += __shfl_xor_sync(0xffffffffu, lm1, 1);
    lm1 += __shfl_xor_sync(0xffffffffu, lm1, 2);

    #pragma unroll
    for (int vt = 0; vt < 8; vt++) {
        O[vt][0] *= em0; O[vt][1] *= em0;
        O[vt][2] *= em1; O[vt][3] *= em1;
    }

    __syncthreads();
    if (tm == 0) {
        smf[LBUF + shalf * 64 + prow]     = lm0 * em0;
        smf[LBUF + shalf * 64 + prow + 8] = lm1 * em1;
        smf[MBUF + shalf * 64 + prow]     = m0;
        smf[MBUF + shalf * 64 + prow + 8] = m1;
    }
    if (shalf == 0) {
        #pragma unroll
        for (int vt = 0; vt < 8; vt++) {
            int c = vt * 8 + 2 * tm;
            *(float2*)&smf[OBUF + prow * 68 + c]       = make_float2(O[vt][0], O[vt][1]);
            *(float2*)&smf[OBUF + (prow + 8) * 68 + c] = make_float2(O[vt][2], O[vt][3]);
        }
    }
    __syncthreads();
    if (tid < 64) {
        float inv = 1.0f / (smf[LBUF + tid] + smf[LBUF + 64 + tid]);
        smf[RINV + tid] = inv;
        float mr = fmaxf(smf[MBUF + tid], smf[MBUF + 64 + tid]);
        g_mc[(size_t)b * T_ + t0 + tid] = make_float2(mr, __expf(mr) * inv);
    }
    __syncthreads();

    if (shalf == 1) {
        const float iv0 = smf[RINV + prow];
        const float iv1 = smf[RINV + prow + 8];
        #pragma unroll
        for (int vt = 0; vt < 8; vt++) {
            int c = vt * 8 + 2 * tm;
            float2 pa = *(const float2*)&smf[OBUF + prow * 68 + c];
            float2 pb = *(const float2*)&smf[OBUF + (prow + 8) * 68 + c];
            *(float2*)(oo + (size_t)prow * H_ + c) =
                make_float2((pa.x + O[vt][0]) * iv0, (pa.y + O[vt][1]) * iv0);
            *(float2*)(oo + (size_t)(prow + 8) * H_ + c) =
                make_float2((pb.x + O[vt][2]) * iv1, (pb.y + O[vt][3]) * iv1);
        }
    }
}

// ===================== K2: recompute scores, write final p =====================
// warp layout: 2 row-groups (32 rows = 2 m16 tiles) x 4 strip-quarters (4 strips)
// -> K fragments loaded ONCE per strip, reused across both row tiles (halves LDS)
__global__ void __launch_bounds__(NT, 2)
attn_p2(const float* __restrict__ q, const float* __restrict__ k,
        const int* __restrict__ mask, float* __restrict__ out)
{
    const int tid = threadIdx.x;
    const int w = tid >> 5, lane = tid & 31;
    const int n_ = lane >> 2, tm = lane & 3;
    const int bx = blockIdx.x;
    const int b = bx >> 5, t0 = (bx & 31) << 6;
    const int rgrp = w & 1, squad = w >> 1;      // 2 row-groups x 4 squads
    const int rbase = rgrp * 32;

    const float* qb = q + ((size_t)b * T_ + t0) * H_;
    const float* kb = k + (size_t)b * S_ * H_;
    const int*   mb = mask + (size_t)b * S_;
    float* pp = out + (size_t)B_ * T_ * H_ + ((size_t)b * T_ + t0) * S_;

    // Q fragments for 2 row tiles (rows rbase+rt*16+n_, +8)
    uint32_t qh[2][4][4], ql[2][4][4];
    float mr[4], cf[4];
    #pragma unroll
    for (int rt = 0; rt < 2; rt++) {
        const int pr = rbase + rt * 16 + n_;
        #pragma unroll
        for (int kc = 0; kc < 4; kc++) {
            const int base = kc * 16 + 2 * tm;
            float2 x0 = *(const float2*)(qb + pr * 64 + base);
            float2 x1 = *(const float2*)(qb + (pr + 8) * 64 + base);
            float2 x2 = *(const float2*)(qb + pr * 64 + base + 8);
            float2 x3 = *(const float2*)(qb + (pr + 8) * 64 + base + 8);
            qh[rt][kc][0] = packhl(x0.x, x0.y, ql[rt][kc][0]);
            qh[rt][kc][1] = packhl(x1.x, x1.y, ql[rt][kc][1]);
            qh[rt][kc][2] = packhl(x2.x, x2.y, ql[rt][kc][2]);
            qh[rt][kc][3] = packhl(x3.x, x3.y, ql[rt][kc][3]);
        }
        float2 mc0 = g_mc[(size_t)b * T_ + t0 + pr];
        float2 mc1 = g_mc[(size_t)b * T_ + t0 + pr + 8];
        mr[rt * 2 + 0] = mc0.x; cf[rt * 2 + 0] = mc0.y;
        mr[rt * 2 + 1] = mc1.x; cf[rt * 2 + 1] = mc1.y;
    }

    #pragma unroll
    for (int i = 0; i < 8; i++) {
        int s = i * 256 + tid;
        unsigned bal = __ballot_sync(0xffffffffu, mb[s] != 0);
        if (lane == 0) smu[BITARR2 + i * 8 + w] = bal;
    }

    const int ks_s  = tid >> 4;
    const int ks_k4 = (tid & 15) * 4;
    const int kt0 = ks_k4 >> 1;
    const int kpb = kt0 & ~7;
    const int ku0 = kt0 & 7;
    const int kp0 = kpb + 2 * (ku0 & 3) + (ku0 >> 2);
    const int kp1 = kp0 + 2;

    for (int j = 0; j < 16; j++) {
        const int s0 = j << 7;
        __syncthreads();

        const float* kt = kb + (size_t)s0 * H_;
        #pragma unroll
        for (int it = 0; it < 8; it++) {
            int s = ks_s + it * 16;
            float4 x = *(const float4*)(kt + s * 64 + ks_k4);
            uint32_t l0, l1;
            uint32_t h0 = packhl(x.x, x.y, l0);
            uint32_t h1 = packhl(x.z, x.w, l1);
            smu[KHI + s * 40 + kp0] = h0;
            smu[KHI + s * 40 + kp1] = h1;
            smu[KLO + s * 40 + kp0] = l0;
            smu[KLO + s * 40 + kp1] = l1;
        }
        __syncthreads();

        #pragma unroll
        for (int st = 0; st < 4; st++) {
            const int strip = squad * 4 + st;
            const int kb0 = (strip * 8 + n_) * 40 + 2 * tm;
            // load K fragments ONCE for this strip
            uint2 bh[4], bl[4];
            #pragma unroll
            for (int kc = 0; kc < 4; kc++) {
                bh[kc] = *(const uint2*)&smu[KHI + kb0 + kc * 8];
                bl[kc] = *(const uint2*)&smu[KLO + kb0 + kc * 8];
            }
            uint32_t wb = smu[BITARR2 + j * 4 + (strip >> 2)];
            int sh = ((strip & 3) << 3) + 2 * tm;
            bool b0 = (wb >> sh) & 1u, b1 = (wb >> (sh + 1)) & 1u;
            const int cg = strip * 8 + 2 * tm;

            #pragma unroll
            for (int rt = 0; rt < 2; rt++) {
                float dh[4] = {0.f,0.f,0.f,0.f}, dm[4] = {0.f,0.f,0.f,0.f}, dl[4] = {0.f,0.f,0.f,0.f};
                #pragma unroll
                for (int kc = 0; kc < 4; kc++) {
                    mma16(dh, qh[rt][kc], bh[kc].x, bh[kc].y);
                    mma16(dm, ql[rt][kc], bh[kc].x, bh[kc].y);
                    mma16(dl, qh[rt][kc], bl[kc].x, bl[kc].y);
                }
                float s00 = dh[0] + dm[0] + dl[0];
                float s01 = dh[1] + dm[1] + dl[1];
                float s10 = dh[2] + dm[2] + dl[2];
                float s11 = dh[3] + dm[3] + dl[3];
                const float m0r = mr[rt * 2 + 0], c0r = cf[rt * 2 + 0];
                const float m1r = mr[rt * 2 + 1], c1r = cf[rt * 2 + 1];
                float p00 = b0 ? __expf(s00 - m0r) * c0r : 0.0f;
                float p01 = b1 ? __expf(s01 - m0r) * c0r : 0.0f;
                float p10 = b0 ? __expf(s10 - m1r) * c1r : 0.0f;
                float p11 = b1 ? __expf(s11 - m1r) * c1r : 0.0f;
                const int pr = rbase + rt * 16 + n_;
                __stcs((float2*)(pp + (size_t)pr * S_ + s0 + cg), make_float2(p00, p01));
                __stcs((float2*)(pp + (size_t)(pr + 8) * S_ + s0 + cg), make_float2(p10, p11));
            }
        }
    }
}

extern "C" void kernel_launch(void* const* d_in, const int* in_sizes, int n_in,
                              void* d_out, int out_size)
{
    const float* q    = (const float*)d_in[0];
    const float* keys = (const float*)d_in[1];
    const float* vals = (const float*)d_in[2];
    const int*   mask = (const int*)d_in[3];
    float* out = (float*)d_out;

    cudaFuncSetAttribute(attn_p1, cudaFuncAttributeMaxDynamicSharedMemorySize, SMEM_BYTES);
    cudaFuncSetAttribute(attn_p2, cudaFuncAttributeMaxDynamicSharedMemorySize, SMEM2_BYTES);
    attn_p1<<<B_ * (T_ / 64), NT, SMEM_BYTES>>>(q, keys, vals, mask, out);
    attn_p2<<<B_ * (T_ / 64), NT, SMEM2_BYTES>>>(q, keys, mask, out);
}

// round 16
// speedup vs baseline: 1.0113x; 1.0051x over previous
#include <cuda_runtime.h>
#include <cuda_fp16.h>
#include <cstdint>

static constexpr int B_ = 8, T_ = 2048, S_ = 2048, H_ = 64;
static constexpr int NT = 256;

// per-row (m_ref, coef) scratch between the two kernels
__device__ float2 g_mc[B_ * T_];

// ---------- K1 smem layout (u32 units) ----------
static constexpr int KHI = 0;        // K hi: [s:128][pos:32] stride 40, pair-interleaved
static constexpr int KLO = 5120;
static constexpr int VHI = 10240;    // V hi: [h:64][pos:64] stride 72, interleave + XOR swizzle
static constexpr int CIDXU  = 14848;
static constexpr int BITARR = 15936;
static constexpr int OFFU   = 16000;
static constexpr int RINV   = 16064;
static constexpr int LBUF   = 16128;
static constexpr int MBUF   = 16256;
static constexpr int SEFFU  = 16384;
static constexpr int SMEMU  = 16388;
static constexpr int SMEM_BYTES = SMEMU * 4;   // ~64 KB -> 2 CTAs/SM
static constexpr int OBUF = 0;

// ---------- K2 smem layout ----------
static constexpr int BITARR2 = 10240;  // 32 u32 (this CTA's s-half)
static constexpr int SMEMU2  = 10272;
static constexpr int SMEM2_BYTES = SMEMU2 * 4; // ~41 KB -> 3 CTAs/SM

__device__ __forceinline__ void mma16(float* d, const uint32_t* a, uint32_t b0, uint32_t b1) {
    asm volatile(
        "mma.sync.aligned.m16n8k16.row.col.f32.f16.f16.f32 "
        "{%0,%1,%2,%3}, {%4,%5,%6,%7}, {%8,%9}, {%0,%1,%2,%3};"
        : "+f"(d[0]), "+f"(d[1]), "+f"(d[2]), "+f"(d[3])
        : "r"(a[0]), "r"(a[1]), "r"(a[2]), "r"(a[3]), "r"(b0), "r"(b1));
}

__device__ __forceinline__ uint32_t packhl(float x, float y, uint32_t& lo) {
    __half hx = __float2half_rn(x), hy = __float2half_rn(y);
    __half2 L = __floats2half2_rn(x - __half2float(hx), y - __half2float(hy));
    __half2 Hh = __halves2half2(hx, hy);
    lo = *(uint32_t*)&L;
    return *(uint32_t*)&Hh;
}

__device__ __forceinline__ uint32_t packh(float x, float y) {
    __half2 Hh = __floats2half2_rn(x, y);
    return *(uint32_t*)&Hh;
}

__device__ __forceinline__ int swzv(int h) {
    return ((h & 3) << 1) ^ (((h >> 2) & 7) << 2);
}

extern __shared__ uint32_t smu[];

// ===================== K1: stats + O (compacted flash) =====================
__global__ void __launch_bounds__(NT, 2)
attn_p1(const float* __restrict__ q, const float* __restrict__ k,
        const float* __restrict__ v, const int* __restrict__ mask,
        float* __restrict__ out)
{
    const int tid = threadIdx.x;
    const int w = tid >> 5, lane = tid & 31;
    const int n_ = lane >> 2, tm = lane & 3;
    const int bx = blockIdx.x;
    const int b = bx >> 5, t0 = (bx & 31) << 6;
    const int slab = w & 3, shalf = w >> 2;

    const float* qb = q + ((size_t)b * T_ + t0) * H_;
    const float* kb = k + (size_t)b * S_ * H_;
    const float* vb = v + (size_t)b * S_ * H_;
    const int*   mb = mask + (size_t)b * S_;
    float* oo = out + ((size_t)b * T_ + t0) * H_;

    float* smf = (float*)smu;
    unsigned short* cidx = (unsigned short*)(smu + CIDXU);
    const int prow = 16 * slab + n_;

    uint32_t qh[4][4], ql[4][4];
    #pragma unroll
    for (int kc = 0; kc < 4; kc++) {
        const int base = kc * 16 + 2 * tm;
        float2 x0 = *(const float2*)(qb + prow * 64 + base);
        float2 x1 = *(const float2*)(qb + (prow + 8) * 64 + base);
        float2 x2 = *(const float2*)(qb + prow * 64 + base + 8);
        float2 x3 = *(const float2*)(qb + (prow + 8) * 64 + base + 8);
        qh[kc][0] = packhl(x0.x, x0.y, ql[kc][0]);
        qh[kc][1] = packhl(x1.x, x1.y, ql[kc][1]);
        qh[kc][2] = packhl(x2.x, x2.y, ql[kc][2]);
        qh[kc][3] = packhl(x3.x, x3.y, ql[kc][3]);
    }

    #pragma unroll
    for (int i = 0; i < 8; i++) {
        int s = i * 256 + tid;
        unsigned bal = __ballot_sync(0xffffffffu, mb[s] != 0);
        if (lane == 0) smu[BITARR + i * 8 + w] = bal;
    }
    __syncthreads();
    if (tid == 0) {
        int acc = 0;
        for (int c = 0; c < 64; c++) { smu[OFFU + c] = acc; acc += __popc(smu[BITARR + c]); }
        smu[SEFFU] = acc;
    }
    __syncthreads();
    const int seff = (int)smu[SEFFU];
    const int ntiles = (seff + 127) >> 7;
    const int npad = ntiles << 7;
    if (tid < 64) {
        uint32_t bits = smu[BITARR + tid];
        int o = (int)smu[OFFU + tid];
        int base = tid * 32;
        while (bits) { int bb = __ffs(bits) - 1; cidx[o++] = (unsigned short)(base + bb); bits &= bits - 1; }
    }
    for (int i = tid; i < npad; i += NT) if (i >= seff) cidx[i] = 0xFFFFu;

    float O[8][4];
    #pragma unroll
    for (int i = 0; i < 8; i++)
        #pragma unroll
        for (int jj = 0; jj < 4; jj++) O[i][jj] = 0.0f;
    float m0 = -3.0e38f, m1 = -3.0e38f, lm0 = 0.0f, lm1 = 0.0f;
    float em0 = 0.0f, em1 = 0.0f;
    const float LOGT = 10.0f;

    const int ks_s  = tid >> 4;
    const int ks_k4 = (tid & 15) * 4;
    const int kt0 = ks_k4 >> 1;
    const int kpb = kt0 & ~7;
    const int ku0 = kt0 & 7;
    const int kp0 = kpb + 2 * (ku0 & 3) + (ku0 >> 2);
    const int kp1 = kp0 + 2;
    const int vs_spb = w * 2 + (lane >> 4);
    const int vs_cc  = 4 * (lane & 15);

    for (int j = 0; j < ntiles; j++) {
        const int s0c = j << 7;
        __syncthreads();

        #pragma unroll
        for (int it = 0; it < 8; it++) {
            int s = ks_s + it * 16;
            int orig = cidx[s0c + s];
            float4 x = make_float4(0.f, 0.f, 0.f, 0.f);
            if (orig != 0xFFFF) x = *(const float4*)(kb + (size_t)orig * H_ + ks_k4);
            uint32_t l0, l1;
            uint32_t h0 = packhl(x.x, x.y, l0);
            uint32_t h1 = packhl(x.z, x.w, l1);
            smu[KHI + s * 40 + kp0] = h0;
            smu[KHI + s * 40 + kp1] = h1;
            smu[KLO + s * 40 + kp0] = l0;
            smu[KLO + s * 40 + kp1] = l1;
        }
        #pragma unroll
        for (int it = 0; it < 4; it++) {
            int sp = vs_spb + it * 16;
            int o0 = cidx[s0c + 2 * sp], o1 = cidx[s0c + 2 * sp + 1];
            float4 a  = make_float4(0.f, 0.f, 0.f, 0.f);
            float4 b4 = make_float4(0.f, 0.f, 0.f, 0.f);
            if (o0 != 0xFFFF) a  = *(const float4*)(vb + (size_t)o0 * H_ + vs_cc);
            if (o1 != 0xFFFF) b4 = *(const float4*)(vb + (size_t)o1 * H_ + vs_cc);
            int qp = (sp & ~7) + 2 * (sp & 3) + ((sp >> 2) & 1);
            smu[VHI + (vs_cc + 0) * 72 + (qp ^ swzv(vs_cc + 0))] = packh(a.x, b4.x);
            smu[VHI + (vs_cc + 1) * 72 + (qp ^ swzv(vs_cc + 1))] = packh(a.y, b4.y);
            smu[VHI + (vs_cc + 2) * 72 + (qp ^ swzv(vs_cc + 2))] = packh(a.z, b4.z);
            smu[VHI + (vs_cc + 3) * 72 + (qp ^ swzv(vs_cc + 3))] = packh(a.w, b4.w);
        }
        __syncthreads();

        #pragma unroll 2
        for (int ntp = 0; ntp < 4; ntp++) {
            const int ntpg = shalf * 4 + ntp;
            float sv[2][4];
            bool bt[2][2];
            #pragma unroll
            for (int si = 0; si < 2; si++) {
                const int strip = ntpg * 2 + si;
                float dh[4] = {0.f,0.f,0.f,0.f}, dm[4] = {0.f,0.f,0.f,0.f}, dl[4] = {0.f,0.f,0.f,0.f};
                const int kb0 = (strip * 8 + n_) * 40 + 2 * tm;
                #pragma unroll
                for (int kc = 0; kc < 4; kc++) {
                    uint2 bh = *(const uint2*)&smu[KHI + kb0 + kc * 8];
                    uint2 bl = *(const uint2*)&smu[KLO + kb0 + kc * 8];
                    mma16(dh, qh[kc], bh.x, bh.y);
                    mma16(dm, ql[kc], bh.x, bh.y);
                    mma16(dl, qh[kc], bl.x, bl.y);
                }
                #pragma unroll
                for (int x = 0; x < 4; x++) sv[si][x] = dh[x] + dm[x] + dl[x];
                const int cg = strip * 8 + 2 * tm;
                uint32_t pr = *(const uint32_t*)&cidx[s0c + cg];
                bt[si][0] = ((pr & 0xFFFFu) != 0xFFFFu);
                bt[si][1] = ((pr >> 16) != 0xFFFFu);
            }
            float t0_ = -3.0e38f, t1_ = -3.0e38f;
            #pragma unroll
            for (int si = 0; si < 2; si++) {
                if (bt[si][0]) { t0_ = fmaxf(t0_, sv[si][0]); t1_ = fmaxf(t1_, sv[si][2]); }
                if (bt[si][1]) { t0_ = fmaxf(t0_, sv[si][1]); t1_ = fmaxf(t1_, sv[si][3]); }
            }
            bool big = (t0_ > m0 + LOGT) || (t1_ > m1 + LOGT);
            if (__any_sync(0xffffffffu, big)) {
                t0_ = fmaxf(t0_, __shfl_xor_sync(0xffffffffu, t0_, 1));
                t0_ = fmaxf(t0_, __shfl_xor_sync(0xffffffffu, t0_, 2));
                t1_ = fmaxf(t1_, __shfl_xor_sync(0xffffffffu, t1_, 1));
                t1_ = fmaxf(t1_, __shfl_xor_sync(0xffffffffu, t1_, 2));
                float m0n = fmaxf(m0, t0_), m1n = fmaxf(m1, t1_);
                float f0 = __expf(m0 - m0n), f1 = __expf(m1 - m1n);
                lm0 *= f0; lm1 *= f1;
                #pragma unroll
                for (int vt = 0; vt < 8; vt++) {
                    O[vt][0] *= f0; O[vt][1] *= f0;
                    O[vt][2] *= f1; O[vt][3] *= f1;
                }
                m0 = m0n; m1 = m1n;
                em0 = __expf(m0); em1 = __expf(m1);
            }

            float e[2][4];
            #pragma unroll
            for (int si = 0; si < 2; si++) {
                e[si][0] = bt[si][0] ? __expf(sv[si][0] - m0) : 0.0f;
                e[si][1] = bt[si][1] ? __expf(sv[si][1] - m0) : 0.0f;
                e[si][2] = bt[si][0] ? __expf(sv[si][2] - m1) : 0.0f;
                e[si][3] = bt[si][1] ? __expf(sv[si][3] - m1) : 0.0f;
                lm0 += e[si][0] + e[si][1];
                lm1 += e[si][2] + e[si][3];
            }
            uint32_t pah[4], pal[4];
            pah[0] = packhl(e[0][0], e[0][1], pal[0]);
            pah[1] = packhl(e[0][2], e[0][3], pal[1]);
            pah[2] = packhl(e[1][0], e[1][1], pal[2]);
            pah[3] = packhl(e[1][2], e[1][3], pal[3]);

            const int xbase = ntpg * 8 + 2 * tm;
            #pragma unroll
            for (int vt = 0; vt < 8; vt++) {
                const int h = vt * 8 + n_;
                uint2 vv = *(const uint2*)&smu[VHI + h * 72 + (xbase ^ swzv(h))];
                mma16(O[vt], pah, vv.x, vv.y);
                mma16(O[vt], pal, vv.x, vv.y);
            }
        }
    }

    // ---- epilogue: combine halves, write O and per-row (m_ref, coef) ----
    lm0 += __shfl_xor_sync(0xffffffffu, lm0, 1);
    lm0 += __shfl_xor_sync(0xffffffffu, lm0, 2);
    lm1 += __shfl_xor_sync(0xffffffffu, lm1, 1);
    lm1 += __shfl_xor_sync(0xffffffffu, lm1, 2);

    #pragma unroll
    for (int vt = 0; vt < 8; vt++) {
        O[vt][0] *= em0; O[vt][1] *= em0;
        O[vt][2] *= em1; O[vt][3] *= em1;
    }

    __syncthreads();
    if (tm == 0) {
        smf[LBUF + shalf * 64 + prow]     = lm0 * em0;
        smf[LBUF + shalf * 64 + prow + 8] = lm1 * em1;
        smf[MBUF + shalf * 64 + prow]     = m0;
        smf[MBUF + shalf * 64 + prow + 8] = m1;
    }
    if (shalf == 0) {
        #pragma unroll
        for (int vt = 0; vt < 8; vt++) {
            int c = vt * 8 + 2 * tm;
            *(float2*)&smf[OBUF + prow * 68 + c]       = make_float2(O[vt][0], O[vt][1]);
            *(float2*)&smf[OBUF + (prow + 8) * 68 + c] = make_float2(O[vt][2], O[vt][3]);
        }
    }
    __syncthreads();
    if (tid < 64) {
        float inv = 1.0f / (smf[LBUF + tid] + smf[LBUF + 64 + tid]);
        smf[RINV + tid] = inv;
        float mr = fmaxf(smf[MBUF + tid], smf[MBUF + 64 + tid]);
        g_mc[(size_t)b * T_ + t0 + tid] = make_float2(mr, __expf(mr) * inv);
    }
    __syncthreads();

    if (shalf == 1) {
        const float iv0 = smf[RINV + prow];
        const float iv1 = smf[RINV + prow + 8];
        #pragma unroll
        for (int vt = 0; vt < 8; vt++) {
            int c = vt * 8 + 2 * tm;
            float2 pa = *(const float2*)&smf[OBUF + prow * 68 + c];
            float2 pb = *(const float2*)&smf[OBUF + (prow + 8) * 68 + c];
            *(float2*)(oo + (size_t)prow * H_ + c) =
                make_float2((pa.x + O[vt][0]) * iv0, (pa.y + O[vt][1]) * iv0);
            *(float2*)(oo + (size_t)(prow + 8) * H_ + c) =
                make_float2((pb.x + O[vt][2]) * iv1, (pb.y + O[vt][3]) * iv1);
        }
    }
}

// ===================== K2: recompute scores, write final p =====================
// grid = 512: each CTA covers 64 t-rows x 1024 s-cols (s-half), 3 CTAs/SM
__global__ void __launch_bounds__(NT, 3)
attn_p2(const float* __restrict__ q, const float* __restrict__ k,
        const int* __restrict__ mask, float* __restrict__ out)
{
    const int tid = threadIdx.x;
    const int w = tid >> 5, lane = tid & 31;
    const int n_ = lane >> 2, tm = lane & 3;
    const int bx = blockIdx.x;
    const int b = bx >> 6;
    const int t0 = ((bx >> 1) & 31) << 6;
    const int sbase = (bx & 1) << 10;           // this CTA's s-half
    const int slab = w & 3, shalf = w >> 2;

    const float* qb = q + ((size_t)b * T_ + t0) * H_;
    const float* kb = k + (size_t)b * S_ * H_;
    const int*   mb = mask + (size_t)b * S_;
    float* pp = out + (size_t)B_ * T_ * H_ + ((size_t)b * T_ + t0) * S_;

    const int prow = 16 * slab + n_;

    uint32_t qh[4][4], ql[4][4];
    #pragma unroll
    for (int kc = 0; kc < 4; kc++) {
        const int base = kc * 16 + 2 * tm;
        float2 x0 = *(const float2*)(qb + prow * 64 + base);
        float2 x1 = *(const float2*)(qb + (prow + 8) * 64 + base);
        float2 x2 = *(const float2*)(qb + prow * 64 + base + 8);
        float2 x3 = *(const float2*)(qb + (prow + 8) * 64 + base + 8);
        qh[kc][0] = packhl(x0.x, x0.y, ql[kc][0]);
        qh[kc][1] = packhl(x1.x, x1.y, ql[kc][1]);
        qh[kc][2] = packhl(x2.x, x2.y, ql[kc][2]);
        qh[kc][3] = packhl(x3.x, x3.y, ql[kc][3]);
    }

    float2 mc0 = g_mc[(size_t)b * T_ + t0 + prow];
    float2 mc1 = g_mc[(size_t)b * T_ + t0 + prow + 8];
    const float mr0 = mc0.x, cf0 = mc0.y;
    const float mr1 = mc1.x, cf1 = mc1.y;

    // mask ballots for this CTA's s-half only (1024 cols -> 32 u32)
    #pragma unroll
    for (int i = 0; i < 4; i++) {
        int s = sbase + i * 256 + tid;
        unsigned bal = __ballot_sync(0xffffffffu, mb[s] != 0);
        if (lane == 0) smu[BITARR2 + i * 8 + w] = bal;
    }

    const int ks_s  = tid >> 4;
    const int ks_k4 = (tid & 15) * 4;
    const int kt0 = ks_k4 >> 1;
    const int kpb = kt0 & ~7;
    const int ku0 = kt0 & 7;
    const int kp0 = kpb + 2 * (ku0 & 3) + (ku0 >> 2);
    const int kp1 = kp0 + 2;

    for (int j = 0; j < 8; j++) {
        const int s0 = sbase + (j << 7);
        __syncthreads();

        const float* kt = kb + (size_t)s0 * H_;
        #pragma unroll
        for (int it = 0; it < 8; it++) {
            int s = ks_s + it * 16;
            float4 x = *(const float4*)(kt + s * 64 + ks_k4);
            uint32_t l0, l1;
            uint32_t h0 = packhl(x.x, x.y, l0);
            uint32_t h1 = packhl(x.z, x.w, l1);
            smu[KHI + s * 40 + kp0] = h0;
            smu[KHI + s * 40 + kp1] = h1;
            smu[KLO + s * 40 + kp0] = l0;
            smu[KLO + s * 40 + kp1] = l1;
        }
        __syncthreads();

        #pragma unroll 2
        for (int ntp = 0; ntp < 4; ntp++) {
            const int ntpg = shalf * 4 + ntp;
            #pragma unroll
            for (int si = 0; si < 2; si++) {
                const int strip = ntpg * 2 + si;
                float dh[4] = {0.f,0.f,0.f,0.f}, dm[4] = {0.f,0.f,0.f,0.f}, dl[4] = {0.f,0.f,0.f,0.f};
                const int kb0 = (strip * 8 + n_) * 40 + 2 * tm;
                #pragma unroll
                for (int kc = 0; kc < 4; kc++) {
                    uint2 bh = *(const uint2*)&smu[KHI + kb0 + kc * 8];
                    uint2 bl = *(const uint2*)&smu[KLO + kb0 + kc * 8];
                    mma16(dh, qh[kc], bh.x, bh.y);
                    mma16(dm, ql[kc], bh.x, bh.y);
                    mma16(dl, qh[kc], bl.x, bl.y);
                }
                const int cg = strip * 8 + 2 * tm;
                uint32_t wb = smu[BITARR2 + j * 4 + (strip >> 2)];
                int sh = ((strip & 3) << 3) + 2 * tm;
                bool b0 = (wb >> sh) & 1u, b1 = (wb >> (sh + 1)) & 1u;
                float s00 = dh[0] + dm[0] + dl[0];
                float s01 = dh[1] + dm[1] + dl[1];
                float s10 = dh[2] + dm[2] + dl[2];
                float s11 = dh[3] + dm[3] + dl[3];
                float p00 = b0 ? __expf(s00 - mr0) * cf0 : 0.0f;
                float p01 = b1 ? __expf(s01 - mr0) * cf0 : 0.0f;
                float p10 = b0 ? __expf(s10 - mr1) * cf1 : 0.0f;
                float p11 = b1 ? __expf(s11 - mr1) * cf1 : 0.0f;
                __stcs((float2*)(pp + (size_t)prow * S_ + s0 + cg), make_float2(p00, p01));
                __stcs((float2*)(pp + (size_t)(prow + 8) * S_ + s0 + cg), make_float2(p10, p11));
            }
        }
    }
}

extern "C" void kernel_launch(void* const* d_in, const int* in_sizes, int n_in,
                              void* d_out, int out_size)
{
    const float* q    = (const float*)d_in[0];
    const float* keys = (const float*)d_in[1];
    const float* vals = (const float*)d_in[2];
    const int*   mask = (const int*)d_in[3];
    float* out = (float*)d_out;

    cudaFuncSetAttribute(attn_p1, cudaFuncAttributeMaxDynamicSharedMemorySize, SMEM_BYTES);
    cudaFuncSetAttribute(attn_p2, cudaFuncAttributeMaxDynamicSharedMemorySize, SMEM2_BYTES);
    attn_p1<<<B_ * (T_ / 64), NT, SMEM_BYTES>>>(q, keys, vals, mask, out);
    attn_p2<<<B_ * (T_ / 64) * 2, NT, SMEM2_BYTES>>>(q, keys, mask, out);
}